// round 3
// baseline (speedup 1.0000x reference)
#include <cuda_runtime.h>
#include <cstddef>
#include <cstdint>

#define HW 4096          // 64*64 spatial positions
#define B  2             // batch

// ---------------------------------------------------------------------------
// Scratch (static device globals — no allocation allowed in kernel_launch)
// ---------------------------------------------------------------------------
__device__ float g_M [(size_t)B * HW * HW];   // M[b][j][i] = relu(c3n)*relu(c4n)
__device__ float g_MT[(size_t)B * HW * HW];   // M transposed: MT[b][i][j]
__device__ float g_inorm[4][B * HW];          // 0:src3 1:tgt3 2:src4 3:tgt4

// ---------------------------------------------------------------------------
// 1) inverse L2 norms over channel dim:  1/sqrt(sum_c f^2 + 1e-6)
//    feat layout: [b][c][p], p contiguous (4096)
// ---------------------------------------------------------------------------
__global__ void inv_norm_kernel(const float* __restrict__ f, int slot, int K)
{
    __shared__ float red[4][64];
    int sl = threadIdx.x;          // 0..63 (spatial, coalesced)
    int cg = threadIdx.y;          // 0..3  (channel group)
    int p  = blockIdx.x * 64 + sl; // 0..8191
    int b  = p >> 12;
    int s  = p & (HW - 1);

    const float* fp = f + (size_t)b * K * HW + s;
    int kq = K >> 2;
    int c0 = cg * kq, c1 = c0 + kq;
    float sum = 0.f;
    #pragma unroll 4
    for (int c = c0; c < c1; c++) {
        float v = __ldg(fp + (size_t)c * HW);
        sum = fmaf(v, v, sum);
    }
    red[cg][sl] = sum;
    __syncthreads();
    if (cg == 0) {
        float t = red[0][sl] + red[1][sl] + red[2][sl] + red[3][sl];
        g_inorm[slot][p] = 1.0f / sqrtf(t + 1e-6f);
    }
}

// ---------------------------------------------------------------------------
// 2) fused correlation GEMM:  C[j][i] = relu( inA[j]*inB[i] * sum_k A[k][j]B[k][i] )
//    mode 0: M = C ;  mode 1: M *= C
//    128x128 tile, 256 threads, 8x8 per thread, K-step 8, reg double-buffer
// ---------------------------------------------------------------------------
__global__ __launch_bounds__(256, 2)
void gemm_relu_kernel(const float* __restrict__ A,   // tgt feat [b][K][HW]
                      const float* __restrict__ Bm,  // src feat [b][K][HW]
                      int slotA, int slotB, int K, int mode)
{
    int b = blockIdx.z;
    const float* Ab = A  + (size_t)b * K * HW;
    const float* Bb = Bm + (size_t)b * K * HW;
    float*       Mb = g_M + (size_t)b * HW * HW;

    int j0 = blockIdx.y * 128;
    int i0 = blockIdx.x * 128;

    __shared__ float As[8][128];
    __shared__ float Bs[8][128];

    int tid = threadIdx.x;
    int lr  = tid >> 5;            // 0..7  (k row for loads)
    int lc  = (tid & 31) << 2;     // 0..124 (float4 col)
    int tx  = tid & 15;            // i micro-tile
    int ty  = tid >> 4;            // j micro-tile

    float acc[8][8];
    #pragma unroll
    for (int r = 0; r < 8; r++)
        #pragma unroll
        for (int c = 0; c < 8; c++) acc[r][c] = 0.f;

    const float* Aptr = Ab + (size_t)lr * HW + j0 + lc;
    const float* Bptr = Bb + (size_t)lr * HW + i0 + lc;

    float4 aReg = *(const float4*)Aptr;
    float4 bReg = *(const float4*)Bptr;

    int kTiles = K >> 3;
    for (int kt = 0; kt < kTiles; kt++) {
        *(float4*)&As[lr][lc] = aReg;
        *(float4*)&Bs[lr][lc] = bReg;
        __syncthreads();
        if (kt + 1 < kTiles) {
            aReg = *(const float4*)(Aptr + (size_t)(kt + 1) * 8 * HW);
            bReg = *(const float4*)(Bptr + (size_t)(kt + 1) * 8 * HW);
        }
        #pragma unroll
        for (int kk = 0; kk < 8; kk++) {
            float af[8], bf[8];
            #pragma unroll
            for (int r = 0; r < 8; r++) af[r] = As[kk][ty * 8 + r];
            #pragma unroll
            for (int c = 0; c < 8; c++) bf[c] = Bs[kk][tx * 8 + c];
            #pragma unroll
            for (int r = 0; r < 8; r++)
                #pragma unroll
                for (int c = 0; c < 8; c++)
                    acc[r][c] = fmaf(af[r], bf[c], acc[r][c]);
        }
        __syncthreads();
    }

    // epilogue: scale by inverse norms, relu, write / multiply
    float si[8];
    #pragma unroll
    for (int c = 0; c < 8; c++) si[c] = g_inorm[slotB][b * HW + i0 + tx * 8 + c];

    #pragma unroll
    for (int r = 0; r < 8; r++) {
        int j = j0 + ty * 8 + r;
        float sj = g_inorm[slotA][b * HW + j];
        size_t rowoff = (size_t)j * HW + i0 + tx * 8;
        #pragma unroll
        for (int c = 0; c < 8; c++) {
            float v = fmaxf(acc[r][c] * sj * si[c], 0.f);
            if (mode) Mb[rowoff + c] *= v;
            else      Mb[rowoff + c]  = v;
        }
    }
}

// ---------------------------------------------------------------------------
// 3) transpose M -> MT (per batch 4096x4096), 32x32 smem tiles
// ---------------------------------------------------------------------------
__global__ void transpose_kernel()
{
    __shared__ float tile[32][33];
    int b = blockIdx.z;
    const float* ib = g_M  + (size_t)b * HW * HW;
    float*       ob = g_MT + (size_t)b * HW * HW;

    int x  = blockIdx.x * 32 + threadIdx.x;
    int y0 = blockIdx.y * 32;
    #pragma unroll
    for (int r = 0; r < 4; r++)
        tile[threadIdx.y + r * 8][threadIdx.x] =
            ib[(size_t)(y0 + threadIdx.y + r * 8) * HW + x];
    __syncthreads();
    int x2 = blockIdx.y * 32 + threadIdx.x;
    int y2 = blockIdx.x * 32;
    #pragma unroll
    for (int r = 0; r < 4; r++)
        ob[(size_t)(y2 + threadIdx.y + r * 8) * HW + x2] =
            tile[threadIdx.x][threadIdx.y + r * 8];
}

// ---------------------------------------------------------------------------
// 4) kernel-soft-argmax, one block per row (4096 elements, fits in smem)
//    useMT=1 : rows of MT (= columns of M)  -> s2t grid
//    useMT=0 : rows of M                    -> t2s grid
//    softmax computed WITHOUT max subtraction: exp arg in [0, 50], safe in fp32,
//    identical ratio p_j to the reference (constant factor cancels).
// ---------------------------------------------------------------------------
__global__ __launch_bounds__(256)
void soft_argmax_kernel(int useMT, float* __restrict__ outG)
{
    __shared__ float srow[HW];     // 16 KB
    __shared__ float gx[64], gy[64];
    __shared__ float wsum[8], wmax[8], wS[8], wSY[8];
    __shared__ int   widx[8];
    __shared__ float s_alpha;
    __shared__ int   s_xs, s_ys;

    int row = blockIdx.x & (HW - 1);
    int b   = blockIdx.x >> 12;
    const float* base = useMT ? g_MT : g_M;
    const float4* rp  = (const float4*)(base + (size_t)blockIdx.x * HW);

    int tid  = threadIdx.x;
    int warp = tid >> 5;
    int lane = tid & 31;

    // load row (coalesced float4)
    #pragma unroll
    for (int q = 0; q < 4; q++) {
        float4 v = rp[q * 256 + tid];
        *(float4*)&srow[(q * 256 + tid) * 4] = v;
    }
    __syncthreads();

    // ---- pass A: sum of squares + argmax (first-occurrence tie-break) ----
    float sumsq = 0.f, vmax = -1.f;
    int   imax  = 0;
    #pragma unroll
    for (int q = 0; q < 16; q++) {
        int a = q * 256 + tid;
        float v = srow[a];
        sumsq = fmaf(v, v, sumsq);
        if (v > vmax) { vmax = v; imax = a; }
    }
    #pragma unroll
    for (int off = 16; off > 0; off >>= 1) {
        sumsq += __shfl_down_sync(0xffffffffu, sumsq, off);
        float ov = __shfl_down_sync(0xffffffffu, vmax, off);
        int   oi = __shfl_down_sync(0xffffffffu, imax, off);
        if (ov > vmax || (ov == vmax && oi < imax)) { vmax = ov; imax = oi; }
    }
    if (lane == 0) { wsum[warp] = sumsq; wmax[warp] = vmax; widx[warp] = imax; }
    __syncthreads();
    if (tid == 0) {
        float ss = 0.f, vm = -1.f; int im = 0;
        #pragma unroll
        for (int w = 0; w < 8; w++) {
            ss += wsum[w];
            if (wmax[w] > vm || (wmax[w] == vm && widx[w] < im)) { vm = wmax[w]; im = widx[w]; }
        }
        float norm = sqrtf(ss + 1e-6f);
        s_alpha = 50.f / norm;
        s_xs = im & 63;
        s_ys = im >> 6;
    }
    __syncthreads();

    // separable gaussian tables: exp(-d^2 / (2*sigma^2)), sigma=5 -> *0.02
    if (tid < 64) {
        float dx = (float)(tid - s_xs);
        gx[tid] = __expf(-dx * dx * 0.02f);
    } else if (tid < 128) {
        float dy = (float)((tid - 64) - s_ys);
        gy[tid - 64] = __expf(-dy * dy * 0.02f);
    }
    __syncthreads();

    // ---- pass B: softmax-weighted coordinate sums ----
    float alpha = s_alpha;
    int   xa    = tid & 63;             // constant per thread (256 % 64 == 0)
    float gxv   = gx[xa];
    float xn    = fmaf((float)xa, 2.f / 63.f, -1.f);

    float s = 0.f, sy = 0.f;
    #pragma unroll
    for (int q = 0; q < 16; q++) {
        int a  = q * 256 + tid;
        int ya = a >> 6;
        float v = srow[a];
        float e = __expf(alpha * gxv * gy[ya] * v);
        s += e;
        sy = fmaf(e, fmaf((float)ya, 2.f / 63.f, -1.f), sy);
    }
    float sx = s * xn;

    #pragma unroll
    for (int off = 16; off > 0; off >>= 1) {
        s  += __shfl_down_sync(0xffffffffu, s,  off);
        sx += __shfl_down_sync(0xffffffffu, sx, off);
        sy += __shfl_down_sync(0xffffffffu, sy, off);
    }
    if (lane == 0) { wS[warp] = s; wsum[warp] = sx; wSY[warp] = sy; }
    __syncthreads();
    if (tid == 0) {
        float S = 0.f, SX = 0.f, SY = 0.f;
        #pragma unroll
        for (int w = 0; w < 8; w++) { S += wS[w]; SX += wsum[w]; SY += wSY[w]; }
        int yr = row >> 6, xr = row & 63;
        size_t o = ((size_t)(b * 64 + yr) * 64 + xr) * 2;
        outG[o + 0] = SX / S;
        outG[o + 1] = SY / S;
    }
}

// ---------------------------------------------------------------------------
// launch
// ---------------------------------------------------------------------------
extern "C" void kernel_launch(void* const* d_in, const int* in_sizes, int n_in,
                              void* d_out, int out_size)
{
    const float* src3 = (const float*)d_in[0];
    const float* tgt3 = (const float*)d_in[1];
    const float* src4 = (const float*)d_in[2];
    const float* tgt4 = (const float*)d_in[3];
    float* out = (float*)d_out;

    // inverse norms (slots: 0 src3, 1 tgt3, 2 src4, 3 tgt4)
    dim3 nblk(64, 4);
    inv_norm_kernel<<<128, nblk>>>(src3, 0, 1024);
    inv_norm_kernel<<<128, nblk>>>(tgt3, 1, 1024);
    inv_norm_kernel<<<128, nblk>>>(src4, 2, 2048);
    inv_norm_kernel<<<128, nblk>>>(tgt4, 3, 2048);

    // M = relu(c3n) ; M *= relu(c4n)    (corr[j,i] = <tgt[:,j], src[:,i]>)
    dim3 gg(HW / 128, HW / 128, B);
    gemm_relu_kernel<<<gg, 256>>>(tgt3, src3, 1, 0, 1024, 0);
    gemm_relu_kernel<<<gg, 256>>>(tgt4, src4, 3, 2, 2048, 1);

    // MT for the s2t (column) direction
    transpose_kernel<<<dim3(HW / 32, HW / 32, B), dim3(32, 8)>>>();

    // s2t: columns of M (= rows of MT) -> out[0 .. 16383]
    soft_argmax_kernel<<<B * HW, 256>>>(1, out);
    // t2s: rows of M -> out[32768 .. 49151]
    soft_argmax_kernel<<<B * HW, 256>>>(0, out + 32768);

    // flows are exactly zero in the reference
    cudaMemsetAsync(out + 16384, 0, 16384 * sizeof(float));
    cudaMemsetAsync(out + 49152, 0, 16384 * sizeof(float));
}

// round 6
// speedup vs baseline: 2.2914x; 2.2914x over previous
#include <cuda_runtime.h>
#include <cuda_bf16.h>
#include <cstdint>
#include <cstddef>

#define HW 4096
#define B  2

__device__ __align__(128) float g_M [(size_t)B * HW * HW];
__device__ __align__(128) float g_MT[(size_t)B * HW * HW];
// bf16 split features, layout [b][p][2K]: cols [0,K)=hi, [K,2K)=lo (K-major)
__device__ __align__(128) __nv_bfloat16 g_Xs3[(size_t)B * HW * 2048];
__device__ __align__(128) __nv_bfloat16 g_Xt3[(size_t)B * HW * 2048];
__device__ __align__(128) __nv_bfloat16 g_Xs4[(size_t)B * HW * 4096];
__device__ __align__(128) __nv_bfloat16 g_Xt4[(size_t)B * HW * 4096];
__device__ float g_part[4][64][B * HW];
__device__ float g_inorm[4][B * HW];   // 0:src3 1:tgt3 2:src4 3:tgt4

__device__ __forceinline__ uint32_t smem_u32(const void* p) {
    uint32_t a;
    asm("{ .reg .u64 t; cvta.to.shared.u64 t, %1; cvt.u32.u64 %0, t; }" : "=r"(a) : "l"(p));
    return a;
}
#define CP16(dst, src) \
    asm volatile("cp.async.cg.shared.global [%0], [%1], 16;" :: "r"(dst), "l"(src) : "memory")
#define LDMX4(r, addr) \
    asm volatile("ldmatrix.sync.aligned.m8n8.x4.shared.b16 {%0,%1,%2,%3}, [%4];" \
                 : "=r"((r)[0]), "=r"((r)[1]), "=r"((r)[2]), "=r"((r)[3]) : "r"(addr))
#define MMA16816(c, a, b0, b1) \
    asm volatile("mma.sync.aligned.m16n8k16.row.col.f32.bf16.bf16.f32 " \
                 "{%0,%1,%2,%3},{%4,%5,%6,%7},{%8,%9},{%0,%1,%2,%3};" \
                 : "+f"((c)[0]), "+f"((c)[1]), "+f"((c)[2]), "+f"((c)[3]) \
                 : "r"((a)[0]), "r"((a)[1]), "r"((a)[2]), "r"((a)[3]), "r"(b0), "r"(b1))

// ---------------------------------------------------------------------------
// prep: fp32 [b][c][p] -> bf16 split [b][p][2K] + sum-of-squares partials
// ---------------------------------------------------------------------------
__global__ void prep_kernel(const float* __restrict__ f, int K, int slot)
{
    __shared__ __nv_bfloat16 tH[32][34], tL[32][34];
    __shared__ float red[8][32];
    __nv_bfloat16* X = (slot == 0) ? g_Xs3 : (slot == 1) ? g_Xt3 :
                       (slot == 2) ? g_Xs4 : g_Xt4;

    int tx = threadIdx.x, ty = threadIdx.y;
    int p0 = blockIdx.x * 32, c0 = blockIdx.y * 32, b = blockIdx.z;
    const float* fb = f + (size_t)b * K * HW;

    float sq = 0.f;
    #pragma unroll
    for (int r = 0; r < 4; r++) {
        int c = c0 + ty + 8 * r;
        float v = fb[(size_t)c * HW + p0 + tx];
        __nv_bfloat16 h = __float2bfloat16_rn(v);
        tH[ty + 8 * r][tx] = h;
        tL[ty + 8 * r][tx] = __float2bfloat16_rn(v - __bfloat162float(h));
        sq = fmaf(v, v, sq);
    }
    red[ty][tx] = sq;
    __syncthreads();
    if (ty == 0) {
        float s = 0.f;
        #pragma unroll
        for (int k = 0; k < 8; k++) s += red[k][tx];
        g_part[slot][blockIdx.y][b * HW + p0 + tx] = s;
    }
    int K2 = 2 * K;
    #pragma unroll
    for (int r = 0; r < 4; r++) {
        int p = p0 + ty + 8 * r;
        size_t base = ((size_t)(b * HW + p)) * K2 + c0 + tx;
        X[base]     = tH[tx][ty + 8 * r];
        X[base + K] = tL[tx][ty + 8 * r];
    }
}

__global__ void finalize_norm_kernel()
{
    int idx = blockIdx.x * 256 + threadIdx.x;
    if (idx >= 4 * B * HW) return;
    int slot = idx >> 13, p = idx & (B * HW - 1);
    int nb = (slot < 2) ? 32 : 64;
    float s = 0.f;
    for (int k = 0; k < nb; k++) s += g_part[slot][k][p];
    g_inorm[slot][p] = 1.0f / sqrtf(s + 1e-6f);
}

// ---------------------------------------------------------------------------
// HMMA correlation GEMM (bf16x3): C[j,i] = relu(nA[j]*nB[i]*sum_k A[j,k]B[i,k])
// which=0: res3 (K=1024), mode 0 -> g_M = C
// which=1: res4 (K=2048), mode 1 -> g_M *= C
// CTA tile 128(j) x 128(i), 8 warps (4x2), warp tile 32x64, k-chunk 32,
// 2-stage cp.async; smem rows padded to 80B (conflict-free ldmatrix).
// ---------------------------------------------------------------------------
#define ROWB  80u
#define TILEB (128u * ROWB)        // 10240
#define ST_AH 0u
#define ST_AL TILEB
#define ST_BH (2u * TILEB)
#define ST_BL (3u * TILEB)
#define STAGE (4u * TILEB)         // 40960
#define SMEM_GEMM (2 * 40960)

__global__ __launch_bounds__(256, 2) void gemm_hmma_kernel(int which, int mode,
                                                           int slotA, int slotB)
{
    extern __shared__ char sm[];
    uint32_t su = smem_u32(sm);

    const int K    = which ? 2048 : 1024;
    const int catW = 2 * K;
    const __nv_bfloat16* Ap = which ? g_Xt4 : g_Xt3;   // tgt rows (j)
    const __nv_bfloat16* Bp = which ? g_Xs4 : g_Xs3;   // src cols (i)

    int b  = blockIdx.z;
    int i0 = blockIdx.x * 128, j0 = blockIdx.y * 128;
    int tid = threadIdx.x, lane = tid & 31, warp = tid >> 5;
    int wm = warp & 3, wn = warp >> 2;     // j: wm*32, i: wn*64

    const __nv_bfloat16* Ab = Ap + (size_t)(b * HW + j0) * catW;
    const __nv_bfloat16* Bb = Bp + (size_t)(b * HW + i0) * catW;

    // cp.async geometry: 2 (row,chunk) pairs per thread per sub-tile
    int r0 = tid >> 2, c0c = tid & 3;
    int r1 = (tid + 256) >> 2, c1c = tid & 3;   // rows 0..63 then 64..127

    // ldmatrix lane offsets
    uint32_t aRowOff = (uint32_t)((wm * 32 + ((lane >> 3) & 1) * 8 + (lane & 7)) * 80
                                  + (lane >> 4) * 16);
    uint32_t bRowOff = (uint32_t)((wn * 64 + ((lane >> 4) & 1) * 8 + (lane & 7)) * 80
                                  + ((lane >> 3) & 1) * 16);

    float acc[2][8][4];
    #pragma unroll
    for (int mi = 0; mi < 2; mi++)
        #pragma unroll
        for (int ni = 0; ni < 8; ni++)
            #pragma unroll
            for (int q = 0; q < 4; q++) acc[mi][ni][q] = 0.f;

    const int nch = K >> 5;

    auto loadStage = [&](int ch, int buf) {
        uint32_t st = su + (uint32_t)buf * STAGE;
        int kel = ch * 32;
        // A hi/lo
        {
            const __nv_bfloat16* gA0 = Ab + (size_t)r0 * catW + kel + c0c * 8;
            const __nv_bfloat16* gA1 = Ab + (size_t)r1 * catW + kel + c1c * 8;
            CP16(st + ST_AH + r0 * 80 + c0c * 16, gA0);
            CP16(st + ST_AH + r1 * 80 + c1c * 16, gA1);
            CP16(st + ST_AL + r0 * 80 + c0c * 16, gA0 + K);
            CP16(st + ST_AL + r1 * 80 + c1c * 16, gA1 + K);
        }
        // B hi/lo
        {
            const __nv_bfloat16* gB0 = Bb + (size_t)r0 * catW + kel + c0c * 8;
            const __nv_bfloat16* gB1 = Bb + (size_t)r1 * catW + kel + c1c * 8;
            CP16(st + ST_BH + r0 * 80 + c0c * 16, gB0);
            CP16(st + ST_BH + r1 * 80 + c1c * 16, gB1);
            CP16(st + ST_BL + r0 * 80 + c0c * 16, gB0 + K);
            CP16(st + ST_BL + r1 * 80 + c1c * 16, gB1 + K);
        }
        asm volatile("cp.async.commit_group;" ::: "memory");
    };

    loadStage(0, 0);

    for (int ch = 0; ch < nch; ch++) {
        if (ch + 1 < nch) {
            loadStage(ch + 1, (ch + 1) & 1);
            asm volatile("cp.async.wait_group 1;" ::: "memory");
        } else {
            asm volatile("cp.async.wait_group 0;" ::: "memory");
        }
        __syncthreads();

        uint32_t st = su + (uint32_t)(ch & 1) * STAGE;
        #pragma unroll
        for (int t = 0; t < 3; t++) {
            uint32_t aB = st + ((t == 2) ? ST_AL : ST_AH);
            uint32_t bB = st + ((t == 1) ? ST_BL : ST_BH);
            #pragma unroll
            for (int ks = 0; ks < 2; ks++) {
                uint32_t a[2][4], br[4][4];
                LDMX4(a[0], aB + aRowOff + ks * 32);
                LDMX4(a[1], aB + aRowOff + 1280u + ks * 32);
                #pragma unroll
                for (int np = 0; np < 4; np++)
                    LDMX4(br[np], bB + bRowOff + np * 1280u + ks * 32);
                #pragma unroll
                for (int mi = 0; mi < 2; mi++)
                    #pragma unroll
                    for (int ni = 0; ni < 8; ni++)
                        MMA16816(acc[mi][ni], a[mi],
                                 br[ni >> 1][(ni & 1) * 2], br[ni >> 1][(ni & 1) * 2 + 1]);
            }
        }
        __syncthreads();
    }

    // epilogue
    int rj = j0 + wm * 32 + (lane >> 2);
    int ci = i0 + wn * 64 + (lane & 3) * 2;
    float sj[2][2], si[8][2];
    #pragma unroll
    for (int mi = 0; mi < 2; mi++) {
        sj[mi][0] = g_inorm[slotA][b * HW + rj + mi * 16];
        sj[mi][1] = g_inorm[slotA][b * HW + rj + mi * 16 + 8];
    }
    #pragma unroll
    for (int ni = 0; ni < 8; ni++) {
        si[ni][0] = g_inorm[slotB][b * HW + ci + ni * 8];
        si[ni][1] = g_inorm[slotB][b * HW + ci + ni * 8 + 1];
    }

    size_t mbase = (size_t)b * HW * HW;
    #pragma unroll
    for (int mi = 0; mi < 2; mi++) {
        #pragma unroll
        for (int ni = 0; ni < 8; ni++) {
            int r = rj + mi * 16, c = ci + ni * 8;
            float v00 = fmaxf(acc[mi][ni][0] * sj[mi][0] * si[ni][0], 0.f);
            float v01 = fmaxf(acc[mi][ni][1] * sj[mi][0] * si[ni][1], 0.f);
            float v10 = fmaxf(acc[mi][ni][2] * sj[mi][1] * si[ni][0], 0.f);
            float v11 = fmaxf(acc[mi][ni][3] * sj[mi][1] * si[ni][1], 0.f);
            float2* p0 = (float2*)&g_M[mbase + (size_t)r * HW + c];
            float2* p1 = (float2*)&g_M[mbase + (size_t)(r + 8) * HW + c];
            if (mode) {
                float2 o0 = *p0, o1 = *p1;
                *p0 = make_float2(o0.x * v00, o0.y * v01);
                *p1 = make_float2(o1.x * v10, o1.y * v11);
            } else {
                *p0 = make_float2(v00, v01);
                *p1 = make_float2(v10, v11);
            }
        }
    }
}

// ---------------------------------------------------------------------------
// transpose M -> MT (4096x4096 per batch)
// ---------------------------------------------------------------------------
__global__ void transpose_kernel()
{
    __shared__ float tile[32][33];
    int b = blockIdx.z;
    const float* ib = g_M  + (size_t)b * HW * HW;
    float*       ob = g_MT + (size_t)b * HW * HW;

    int x  = blockIdx.x * 32 + threadIdx.x;
    int y0 = blockIdx.y * 32;
    #pragma unroll
    for (int r = 0; r < 4; r++)
        tile[threadIdx.y + r * 8][threadIdx.x] =
            ib[(size_t)(y0 + threadIdx.y + r * 8) * HW + x];
    __syncthreads();
    int x2 = blockIdx.y * 32 + threadIdx.x;
    int y2 = blockIdx.x * 32;
    #pragma unroll
    for (int r = 0; r < 4; r++)
        ob[(size_t)(y2 + threadIdx.y + r * 8) * HW + x2] =
            tile[threadIdx.x][threadIdx.y + r * 8];
}

// ---------------------------------------------------------------------------
// kernel-soft-argmax (identical to the passing R2 version)
// ---------------------------------------------------------------------------
__global__ __launch_bounds__(256)
void soft_argmax_kernel(int useMT, float* __restrict__ outG)
{
    __shared__ float srow[HW];
    __shared__ float gx[64], gy[64];
    __shared__ float wsum[8], wmax[8], wS[8], wSY[8];
    __shared__ int   widx[8];
    __shared__ float s_alpha;
    __shared__ int   s_xs, s_ys;

    int row = blockIdx.x & (HW - 1);
    int b   = blockIdx.x >> 12;
    const float* base = useMT ? g_MT : g_M;
    const float4* rp  = (const float4*)(base + (size_t)blockIdx.x * HW);

    int tid = threadIdx.x, warp = tid >> 5, lane = tid & 31;

    #pragma unroll
    for (int q = 0; q < 4; q++) {
        float4 v = rp[q * 256 + tid];
        *(float4*)&srow[(q * 256 + tid) * 4] = v;
    }
    __syncthreads();

    float sumsq = 0.f, vmax = -1.f;
    int imax = 0;
    #pragma unroll
    for (int q = 0; q < 16; q++) {
        int a = q * 256 + tid;
        float v = srow[a];
        sumsq = fmaf(v, v, sumsq);
        if (v > vmax) { vmax = v; imax = a; }
    }
    #pragma unroll
    for (int off = 16; off > 0; off >>= 1) {
        sumsq += __shfl_down_sync(0xffffffffu, sumsq, off);
        float ov = __shfl_down_sync(0xffffffffu, vmax, off);
        int   oi = __shfl_down_sync(0xffffffffu, imax, off);
        if (ov > vmax || (ov == vmax && oi < imax)) { vmax = ov; imax = oi; }
    }
    if (lane == 0) { wsum[warp] = sumsq; wmax[warp] = vmax; widx[warp] = imax; }
    __syncthreads();
    if (tid == 0) {
        float ss = 0.f, vm = -1.f; int im = 0;
        #pragma unroll
        for (int w = 0; w < 8; w++) {
            ss += wsum[w];
            if (wmax[w] > vm || (wmax[w] == vm && widx[w] < im)) { vm = wmax[w]; im = widx[w]; }
        }
        s_alpha = 50.f / sqrtf(ss + 1e-6f);
        s_xs = im & 63;
        s_ys = im >> 6;
    }
    __syncthreads();

    if (tid < 64) {
        float dx = (float)(tid - s_xs);
        gx[tid] = __expf(-dx * dx * 0.02f);
    } else if (tid < 128) {
        float dy = (float)((tid - 64) - s_ys);
        gy[tid - 64] = __expf(-dy * dy * 0.02f);
    }
    __syncthreads();

    float alpha = s_alpha;
    int   xa  = tid & 63;
    float gxv = gx[xa];
    float xn  = fmaf((float)xa, 2.f / 63.f, -1.f);

    float s = 0.f, sy = 0.f;
    #pragma unroll
    for (int q = 0; q < 16; q++) {
        int a  = q * 256 + tid;
        int ya = a >> 6;
        float e = __expf(alpha * gxv * gy[ya] * srow[a]);
        s += e;
        sy = fmaf(e, fmaf((float)ya, 2.f / 63.f, -1.f), sy);
    }
    float sx = s * xn;

    #pragma unroll
    for (int off = 16; off > 0; off >>= 1) {
        s  += __shfl_down_sync(0xffffffffu, s,  off);
        sx += __shfl_down_sync(0xffffffffu, sx, off);
        sy += __shfl_down_sync(0xffffffffu, sy, off);
    }
    if (lane == 0) { wS[warp] = s; wsum[warp] = sx; wSY[warp] = sy; }
    __syncthreads();
    if (tid == 0) {
        float S = 0.f, SX = 0.f, SY = 0.f;
        #pragma unroll
        for (int w = 0; w < 8; w++) { S += wS[w]; SX += wsum[w]; SY += wSY[w]; }
        int yr = row >> 6, xr = row & 63;
        size_t o = ((size_t)(b * 64 + yr) * 64 + xr) * 2;
        outG[o + 0] = SX / S;
        outG[o + 1] = SY / S;
    }
}

// ---------------------------------------------------------------------------
extern "C" void kernel_launch(void* const* d_in, const int* in_sizes, int n_in,
                              void* d_out, int out_size)
{
    const float* src3 = (const float*)d_in[0];
    const float* tgt3 = (const float*)d_in[1];
    const float* src4 = (const float*)d_in[2];
    const float* tgt4 = (const float*)d_in[3];
    float* out = (float*)d_out;

    cudaFuncSetAttribute(gemm_hmma_kernel,
                         cudaFuncAttributeMaxDynamicSharedMemorySize, SMEM_GEMM);

    dim3 pblk(32, 8);
    prep_kernel<<<dim3(HW / 32, 1024 / 32, B), pblk>>>(src3, 1024, 0);
    prep_kernel<<<dim3(HW / 32, 1024 / 32, B), pblk>>>(tgt3, 1024, 1);
    prep_kernel<<<dim3(HW / 32, 2048 / 32, B), pblk>>>(src4, 2048, 2);
    prep_kernel<<<dim3(HW / 32, 2048 / 32, B), pblk>>>(tgt4, 2048, 3);
    finalize_norm_kernel<<<128, 256>>>();

    dim3 gg(HW / 128, HW / 128, B);
    gemm_hmma_kernel<<<gg, 256, SMEM_GEMM>>>(0, 0, 1, 0);   // res3: M  = C3
    gemm_hmma_kernel<<<gg, 256, SMEM_GEMM>>>(1, 1, 3, 2);   // res4: M *= C4

    transpose_kernel<<<dim3(HW / 32, HW / 32, B), dim3(32, 8)>>>();

    soft_argmax_kernel<<<B * HW, 256>>>(1, out);            // s2t (columns of M)
    soft_argmax_kernel<<<B * HW, 256>>>(0, out + 32768);    // t2s (rows of M)

    cudaMemsetAsync(out + 16384, 0, 16384 * sizeof(float));
    cudaMemsetAsync(out + 49152, 0, 16384 * sizeof(float));
}

// round 7
// speedup vs baseline: 2.4838x; 1.0840x over previous
#include <cuda_runtime.h>
#include <cuda_bf16.h>
#include <cstdint>
#include <cstddef>

#define HW 4096
#define B  2

__device__ __align__(128) float g_M [(size_t)B * HW * HW];
__device__ __align__(128) float g_MT[(size_t)B * HW * HW];
// bf16 split features, layout [b][p][2K]: cols [0,K)=hi, [K,2K)=lo (K-major)
__device__ __align__(128) __nv_bfloat16 g_Xs3[(size_t)B * HW * 2048];
__device__ __align__(128) __nv_bfloat16 g_Xt3[(size_t)B * HW * 2048];
__device__ __align__(128) __nv_bfloat16 g_Xs4[(size_t)B * HW * 4096];
__device__ __align__(128) __nv_bfloat16 g_Xt4[(size_t)B * HW * 4096];
__device__ float g_part[4][64][B * HW];
__device__ float g_inorm[4][B * HW];   // 0:src3 1:tgt3 2:src4 3:tgt4

__device__ __forceinline__ uint32_t smem_u32(const void* p) {
    uint32_t a;
    asm("{ .reg .u64 t; cvta.to.shared.u64 t, %1; cvt.u32.u64 %0, t; }" : "=r"(a) : "l"(p));
    return a;
}
#define CP16(dst, src) \
    asm volatile("cp.async.cg.shared.global [%0], [%1], 16;" :: "r"(dst), "l"(src) : "memory")
#define LDMX4(r, addr) \
    asm volatile("ldmatrix.sync.aligned.m8n8.x4.shared.b16 {%0,%1,%2,%3}, [%4];" \
                 : "=r"((r)[0]), "=r"((r)[1]), "=r"((r)[2]), "=r"((r)[3]) : "r"(addr))
#define MMA16816(c, a, b0, b1) \
    asm volatile("mma.sync.aligned.m16n8k16.row.col.f32.bf16.bf16.f32 " \
                 "{%0,%1,%2,%3},{%4,%5,%6,%7},{%8,%9},{%0,%1,%2,%3};" \
                 : "+f"((c)[0]), "+f"((c)[1]), "+f"((c)[2]), "+f"((c)[3]) \
                 : "r"((a)[0]), "r"((a)[1]), "r"((a)[2]), "r"((a)[3]), "r"(b0), "r"(b1))

// ---------------------------------------------------------------------------
// prep (all four tensors in one launch):
// fp32 [b][c][p] -> bf16 split [b][p][2K] + sum-of-squares partials
// blockIdx.y in [0,192): [0,32)=slot0, [32,64)=slot1, [64,128)=slot2, [128,192)=slot3
// ---------------------------------------------------------------------------
__global__ void prep_kernel(const float* __restrict__ f0, const float* __restrict__ f1,
                            const float* __restrict__ f2, const float* __restrict__ f3)
{
    __shared__ __nv_bfloat16 tH[32][34], tL[32][34];
    __shared__ float red[8][32];

    int y = blockIdx.y;
    int slot, cblk;
    const float* f;
    if      (y < 32)  { slot = 0; cblk = y;       f = f0; }
    else if (y < 64)  { slot = 1; cblk = y - 32;  f = f1; }
    else if (y < 128) { slot = 2; cblk = y - 64;  f = f2; }
    else              { slot = 3; cblk = y - 128; f = f3; }
    int K = (slot < 2) ? 1024 : 2048;
    __nv_bfloat16* X = (slot == 0) ? g_Xs3 : (slot == 1) ? g_Xt3 :
                       (slot == 2) ? g_Xs4 : g_Xt4;

    int tx = threadIdx.x, ty = threadIdx.y;
    int p0 = blockIdx.x * 32, c0 = cblk * 32, b = blockIdx.z;
    const float* fb = f + (size_t)b * K * HW;

    float sq = 0.f;
    #pragma unroll
    for (int r = 0; r < 4; r++) {
        int c = c0 + ty + 8 * r;
        float v = fb[(size_t)c * HW + p0 + tx];
        __nv_bfloat16 h = __float2bfloat16_rn(v);
        tH[ty + 8 * r][tx] = h;
        tL[ty + 8 * r][tx] = __float2bfloat16_rn(v - __bfloat162float(h));
        sq = fmaf(v, v, sq);
    }
    red[ty][tx] = sq;
    __syncthreads();
    if (ty == 0) {
        float s = 0.f;
        #pragma unroll
        for (int k = 0; k < 8; k++) s += red[k][tx];
        g_part[slot][cblk][b * HW + p0 + tx] = s;
    }
    int K2 = 2 * K;
    #pragma unroll
    for (int r = 0; r < 4; r++) {
        int p = p0 + ty + 8 * r;
        size_t base = ((size_t)(b * HW + p)) * K2 + c0 + tx;
        X[base]     = tH[tx][ty + 8 * r];
        X[base + K] = tL[tx][ty + 8 * r];
    }
}

__global__ void finalize_norm_kernel()
{
    int idx = blockIdx.x * 256 + threadIdx.x;
    if (idx >= 4 * B * HW) return;
    int slot = idx >> 13, p = idx & (B * HW - 1);
    int nb = (slot < 2) ? 32 : 64;
    float s = 0.f;
    for (int k = 0; k < nb; k++) s += g_part[slot][k][p];
    g_inorm[slot][p] = 1.0f / sqrtf(s + 1e-6f);
}

// ---------------------------------------------------------------------------
// HMMA correlation GEMM (bf16x3, fused-term inner loop):
//   C[j,i] = relu(nA[j]*nB[i]*sum_k A[j,k]B[i,k])
// which=0: res3 (K=1024) -> g_M = C
// which=1: res4 (K=2048) -> v = g_M*C; write g_M AND g_MT (smem transpose)
// CTA 128x128, 8 warps (4x2), warp 32x64, k-chunk 32, 2-stage cp.async.
// ---------------------------------------------------------------------------
#define ROWB  80u
#define TILEB (128u * ROWB)        // 10240
#define ST_AH 0u
#define ST_AL TILEB
#define ST_BH (2u * TILEB)
#define ST_BL (3u * TILEB)
#define STAGE (4u * TILEB)         // 40960
#define SMEM_GEMM (2 * 40960)      // also >= 128*129*4 = 66048 for epilogue

__global__ __launch_bounds__(256, 2) void gemm_hmma_kernel(int which)
{
    extern __shared__ char sm[];
    uint32_t su = smem_u32(sm);

    const int K    = which ? 2048 : 1024;
    const int catW = 2 * K;
    const int slotA = which ? 3 : 1;   // tgt norms (rows j)
    const int slotB = which ? 2 : 0;   // src norms (cols i)
    const __nv_bfloat16* Ap = which ? g_Xt4 : g_Xt3;
    const __nv_bfloat16* Bp = which ? g_Xs4 : g_Xs3;

    int b  = blockIdx.z;
    int i0 = blockIdx.x * 128, j0 = blockIdx.y * 128;
    int tid = threadIdx.x, lane = tid & 31, warp = tid >> 5;
    int wm = warp & 3, wn = warp >> 2;     // j: wm*32, i: wn*64

    const __nv_bfloat16* Ab = Ap + (size_t)(b * HW + j0) * catW;
    const __nv_bfloat16* Bb = Bp + (size_t)(b * HW + i0) * catW;

    int r0 = tid >> 2, cc = tid & 3;
    int r1 = r0 + 64;

    uint32_t aRowOff = (uint32_t)((wm * 32 + ((lane >> 3) & 1) * 8 + (lane & 7)) * 80
                                  + (lane >> 4) * 16);
    uint32_t bRowOff = (uint32_t)((wn * 64 + ((lane >> 4) & 1) * 8 + (lane & 7)) * 80
                                  + ((lane >> 3) & 1) * 16);

    float acc[2][8][4];
    #pragma unroll
    for (int mi = 0; mi < 2; mi++)
        #pragma unroll
        for (int ni = 0; ni < 8; ni++)
            #pragma unroll
            for (int q = 0; q < 4; q++) acc[mi][ni][q] = 0.f;

    const int nch = K >> 5;

    auto loadStage = [&](int ch, int buf) {
        uint32_t st = su + (uint32_t)buf * STAGE;
        int kel = ch * 32;
        const __nv_bfloat16* gA0 = Ab + (size_t)r0 * catW + kel + cc * 8;
        const __nv_bfloat16* gA1 = Ab + (size_t)r1 * catW + kel + cc * 8;
        CP16(st + ST_AH + r0 * 80 + cc * 16, gA0);
        CP16(st + ST_AH + r1 * 80 + cc * 16, gA1);
        CP16(st + ST_AL + r0 * 80 + cc * 16, gA0 + K);
        CP16(st + ST_AL + r1 * 80 + cc * 16, gA1 + K);
        const __nv_bfloat16* gB0 = Bb + (size_t)r0 * catW + kel + cc * 8;
        const __nv_bfloat16* gB1 = Bb + (size_t)r1 * catW + kel + cc * 8;
        CP16(st + ST_BH + r0 * 80 + cc * 16, gB0);
        CP16(st + ST_BH + r1 * 80 + cc * 16, gB1);
        CP16(st + ST_BL + r0 * 80 + cc * 16, gB0 + K);
        CP16(st + ST_BL + r1 * 80 + cc * 16, gB1 + K);
        asm volatile("cp.async.commit_group;" ::: "memory");
    };

    loadStage(0, 0);

    for (int ch = 0; ch < nch; ch++) {
        if (ch + 1 < nch) {
            loadStage(ch + 1, (ch + 1) & 1);
            asm volatile("cp.async.wait_group 1;" ::: "memory");
        } else {
            asm volatile("cp.async.wait_group 0;" ::: "memory");
        }
        __syncthreads();

        uint32_t st = su + (uint32_t)(ch & 1) * STAGE;
        #pragma unroll
        for (int ks = 0; ks < 2; ks++) {
            uint32_t ahi[2][4], alo[2][4], br[4][4];
            // pass 1: bhi shared by hi*hi and lo*hi
            LDMX4(ahi[0], st + ST_AH + aRowOff + ks * 32);
            LDMX4(ahi[1], st + ST_AH + aRowOff + 1280u + ks * 32);
            LDMX4(alo[0], st + ST_AL + aRowOff + ks * 32);
            LDMX4(alo[1], st + ST_AL + aRowOff + 1280u + ks * 32);
            #pragma unroll
            for (int np = 0; np < 4; np++)
                LDMX4(br[np], st + ST_BH + bRowOff + np * 1280u + ks * 32);
            #pragma unroll
            for (int mi = 0; mi < 2; mi++)
                #pragma unroll
                for (int ni = 0; ni < 8; ni++)
                    MMA16816(acc[mi][ni], ahi[mi],
                             br[ni >> 1][(ni & 1) * 2], br[ni >> 1][(ni & 1) * 2 + 1]);
            #pragma unroll
            for (int mi = 0; mi < 2; mi++)
                #pragma unroll
                for (int ni = 0; ni < 8; ni++)
                    MMA16816(acc[mi][ni], alo[mi],
                             br[ni >> 1][(ni & 1) * 2], br[ni >> 1][(ni & 1) * 2 + 1]);
            // pass 2: blo with live ahi
            #pragma unroll
            for (int np = 0; np < 4; np++)
                LDMX4(br[np], st + ST_BL + bRowOff + np * 1280u + ks * 32);
            #pragma unroll
            for (int mi = 0; mi < 2; mi++)
                #pragma unroll
                for (int ni = 0; ni < 8; ni++)
                    MMA16816(acc[mi][ni], ahi[mi],
                             br[ni >> 1][(ni & 1) * 2], br[ni >> 1][(ni & 1) * 2 + 1]);
        }
        __syncthreads();
    }

    // ------------------- epilogue -------------------
    int rl = wm * 32 + (lane >> 2);         // local j
    int cl = wn * 64 + (lane & 3) * 2;      // local i
    int rj = j0 + rl, ci = i0 + cl;

    float sj[2][2], si[8][2];
    #pragma unroll
    for (int mi = 0; mi < 2; mi++) {
        sj[mi][0] = g_inorm[slotA][b * HW + rj + mi * 16];
        sj[mi][1] = g_inorm[slotA][b * HW + rj + mi * 16 + 8];
    }
    #pragma unroll
    for (int ni = 0; ni < 8; ni++) {
        si[ni][0] = g_inorm[slotB][b * HW + ci + ni * 8];
        si[ni][1] = g_inorm[slotB][b * HW + ci + ni * 8 + 1];
    }

    size_t mbase = (size_t)b * HW * HW;
    if (which == 0) {
        #pragma unroll
        for (int mi = 0; mi < 2; mi++)
            #pragma unroll
            for (int ni = 0; ni < 8; ni++) {
                int r = rj + mi * 16, c = ci + ni * 8;
                float v00 = fmaxf(acc[mi][ni][0] * sj[mi][0] * si[ni][0], 0.f);
                float v01 = fmaxf(acc[mi][ni][1] * sj[mi][0] * si[ni][1], 0.f);
                float v10 = fmaxf(acc[mi][ni][2] * sj[mi][1] * si[ni][0], 0.f);
                float v11 = fmaxf(acc[mi][ni][3] * sj[mi][1] * si[ni][1], 0.f);
                *(float2*)&g_M[mbase + (size_t)r * HW + c]       = make_float2(v00, v01);
                *(float2*)&g_M[mbase + (size_t)(r + 8) * HW + c] = make_float2(v10, v11);
            }
    } else {
        float* buf = (float*)sm;            // 128 x 129 floats (66 KB)
        #pragma unroll
        for (int mi = 0; mi < 2; mi++)
            #pragma unroll
            for (int ni = 0; ni < 8; ni++) {
                int r = rj + mi * 16, c = ci + ni * 8;
                int lr = rl + mi * 16, lc = cl + ni * 8;
                float v00 = fmaxf(acc[mi][ni][0] * sj[mi][0] * si[ni][0], 0.f);
                float v01 = fmaxf(acc[mi][ni][1] * sj[mi][0] * si[ni][1], 0.f);
                float v10 = fmaxf(acc[mi][ni][2] * sj[mi][1] * si[ni][0], 0.f);
                float v11 = fmaxf(acc[mi][ni][3] * sj[mi][1] * si[ni][1], 0.f);
                float2* p0 = (float2*)&g_M[mbase + (size_t)r * HW + c];
                float2* p1 = (float2*)&g_M[mbase + (size_t)(r + 8) * HW + c];
                float2 o0 = *p0, o1 = *p1;
                float w00 = o0.x * v00, w01 = o0.y * v01;
                float w10 = o1.x * v10, w11 = o1.y * v11;
                *p0 = make_float2(w00, w01);
                *p1 = make_float2(w10, w11);
                buf[lr * 129 + lc]           = w00;
                buf[lr * 129 + lc + 1]       = w01;
                buf[(lr + 8) * 129 + lc]     = w10;
                buf[(lr + 8) * 129 + lc + 1] = w11;
            }
        __syncthreads();
        // transposed write: warp handles 16 columns, lanes cover 128 rows as float4
        #pragma unroll
        for (int it = 0; it < 16; it++) {
            int c = warp * 16 + it;          // local i (column of tile)
            int r = lane * 4;                // local j
            float4 v;
            v.x = buf[(r + 0) * 129 + c];
            v.y = buf[(r + 1) * 129 + c];
            v.z = buf[(r + 2) * 129 + c];
            v.w = buf[(r + 3) * 129 + c];
            *(float4*)&g_MT[mbase + (size_t)(i0 + c) * HW + j0 + r] = v;
        }
    }
}

// ---------------------------------------------------------------------------
// kernel-soft-argmax, both directions in one launch.
// blockIdx >> 13: 0 -> s2t (rows of MT), 1 -> t2s (rows of M)
// ---------------------------------------------------------------------------
__global__ __launch_bounds__(256)
void soft_argmax_kernel(float* __restrict__ out)
{
    __shared__ float srow[HW];
    __shared__ float gx[64], gy[64];
    __shared__ float wsum[8], wmax[8], wS[8], wSY[8];
    __shared__ int   widx[8];
    __shared__ float s_alpha;
    __shared__ int   s_xs, s_ys;

    int dir = blockIdx.x >> 13;
    int sub = blockIdx.x & 8191;
    int row = sub & (HW - 1);
    int b   = sub >> 12;
    const float* base = dir ? g_M : g_MT;
    float* outG = out + dir * 32768;
    const float4* rp = (const float4*)(base + (size_t)sub * HW);

    int tid = threadIdx.x, warp = tid >> 5, lane = tid & 31;

    #pragma unroll
    for (int q = 0; q < 4; q++) {
        float4 v = rp[q * 256 + tid];
        *(float4*)&srow[(q * 256 + tid) * 4] = v;
    }
    __syncthreads();

    float sumsq = 0.f, vmax = -1.f;
    int imax = 0;
    #pragma unroll
    for (int q = 0; q < 16; q++) {
        int a = q * 256 + tid;
        float v = srow[a];
        sumsq = fmaf(v, v, sumsq);
        if (v > vmax) { vmax = v; imax = a; }
    }
    #pragma unroll
    for (int off = 16; off > 0; off >>= 1) {
        sumsq += __shfl_down_sync(0xffffffffu, sumsq, off);
        float ov = __shfl_down_sync(0xffffffffu, vmax, off);
        int   oi = __shfl_down_sync(0xffffffffu, imax, off);
        if (ov > vmax || (ov == vmax && oi < imax)) { vmax = ov; imax = oi; }
    }
    if (lane == 0) { wsum[warp] = sumsq; wmax[warp] = vmax; widx[warp] = imax; }
    __syncthreads();
    if (tid == 0) {
        float ss = 0.f, vm = -1.f; int im = 0;
        #pragma unroll
        for (int w = 0; w < 8; w++) {
            ss += wsum[w];
            if (wmax[w] > vm || (wmax[w] == vm && widx[w] < im)) { vm = wmax[w]; im = widx[w]; }
        }
        s_alpha = 50.f / sqrtf(ss + 1e-6f);
        s_xs = im & 63;
        s_ys = im >> 6;
    }
    __syncthreads();

    if (tid < 64) {
        float dx = (float)(tid - s_xs);
        gx[tid] = __expf(-dx * dx * 0.02f);
    } else if (tid < 128) {
        float dy = (float)((tid - 64) - s_ys);
        gy[tid - 64] = __expf(-dy * dy * 0.02f);
    }
    __syncthreads();

    float alpha = s_alpha;
    int   xa  = tid & 63;
    float gxv = gx[xa];
    float xn  = fmaf((float)xa, 2.f / 63.f, -1.f);

    float s = 0.f, sy = 0.f;
    #pragma unroll
    for (int q = 0; q < 16; q++) {
        int a  = q * 256 + tid;
        int ya = a >> 6;
        float e = __expf(alpha * gxv * gy[ya] * srow[a]);
        s += e;
        sy = fmaf(e, fmaf((float)ya, 2.f / 63.f, -1.f), sy);
    }
    float sx = s * xn;

    #pragma unroll
    for (int off = 16; off > 0; off >>= 1) {
        s  += __shfl_down_sync(0xffffffffu, s,  off);
        sx += __shfl_down_sync(0xffffffffu, sx, off);
        sy += __shfl_down_sync(0xffffffffu, sy, off);
    }
    if (lane == 0) { wS[warp] = s; wsum[warp] = sx; wSY[warp] = sy; }
    __syncthreads();
    if (tid == 0) {
        float S = 0.f, SX = 0.f, SY = 0.f;
        #pragma unroll
        for (int w = 0; w < 8; w++) { S += wS[w]; SX += wsum[w]; SY += wSY[w]; }
        int yr = row >> 6, xr = row & 63;
        size_t o = ((size_t)(b * 64 + yr) * 64 + xr) * 2;
        outG[o + 0] = SX / S;
        outG[o + 1] = SY / S;
    }
}

// ---------------------------------------------------------------------------
extern "C" void kernel_launch(void* const* d_in, const int* in_sizes, int n_in,
                              void* d_out, int out_size)
{
    const float* src3 = (const float*)d_in[0];
    const float* tgt3 = (const float*)d_in[1];
    const float* src4 = (const float*)d_in[2];
    const float* tgt4 = (const float*)d_in[3];
    float* out = (float*)d_out;

    cudaFuncSetAttribute(gemm_hmma_kernel,
                         cudaFuncAttributeMaxDynamicSharedMemorySize, SMEM_GEMM);

    prep_kernel<<<dim3(HW / 32, 192, B), dim3(32, 8)>>>(src3, tgt3, src4, tgt4);
    finalize_norm_kernel<<<128, 256>>>();

    dim3 gg(HW / 128, HW / 128, B);
    gemm_hmma_kernel<<<gg, 256, SMEM_GEMM>>>(0);   // res3: M  = C3
    gemm_hmma_kernel<<<gg, 256, SMEM_GEMM>>>(1);   // res4: M *= C4, MT written too

    soft_argmax_kernel<<<2 * B * HW, 256>>>(out);  // both directions

    cudaMemsetAsync(out + 16384, 0, 16384 * sizeof(float));
    cudaMemsetAsync(out + 49152, 0, 16384 * sizeof(float));
}